// round 3
// baseline (speedup 1.0000x reference)
#include <cuda_runtime.h>
#include <cuda_bf16.h>

#define BCH   10
#define HH    320
#define WW    1024
#define PTS   500
#define DENSE 2000
#define KMEAN 10
#define NPTS  (BCH * PTS)
#define CHUNKS (DENSE / 4)      // 500 int4 chunks per point

__device__ int g_ctr;

__global__ void reset_kernel() { g_ctr = 0; }

// Persistent work-queue kernel: each warp pulls point indices from a global
// atomic counter. Cheap validity check first; only ~25% of points run the
// full gather + k-means. Dynamic fetch => near-perfect load balance.
__global__ __launch_bounds__(128, 4)
void rsbsp_kernel(const float* __restrict__ disp,
                  const float* __restrict__ fore,
                  const int*   __restrict__ cxs,
                  const int*   __restrict__ cys,
                  const int*   __restrict__ bxs,
                  const int*   __restrict__ bys,
                  float*       __restrict__ out)
{
    const int lane = threadIdx.x & 31;

    for (;;) {
        int n = 0;
        if (lane == 0) n = atomicAdd(&g_ctr, 1);
        n = __shfl_sync(0xFFFFFFFFu, n, 0);
        if (n >= NPTS) return;

        const int chan = n / PTS;
        const int cx   = cxs[n];
        const int cy   = cys[n];
        const float* dch = disp + (size_t)chan * (HH * WW);
        const float* fch = fore + (size_t)chan * (HH * WW);

        // ---- validRow: maxpool3x3(|sobel_x(forepred)|)(cy,cx) > 3.1 && disp > 0.007
        // Centers are >= 11 px from every border (zeroArea never reached).
        float g = 0.0f;
        if (lane < 9) {
            const int dy = lane / 3 - 1;
            const int dx = lane % 3 - 1;
            const float* p = fch + (size_t)(cy + dy - 1) * WW + (cx + dx);
            const float a = p[1]  + 2.0f * p[WW + 1] + p[2 * WW + 1];
            const float b = p[-1] + 2.0f * p[WW - 1] + p[2 * WW - 1];
            g = fabsf(a - b);
        }
        #pragma unroll
        for (int o = 16; o; o >>= 1) g = fmaxf(g, __shfl_xor_sync(0xFFFFFFFFu, g, o));

        const int   base = (cy << 10) + cx;      // WW == 1024
        const float dC   = dch[base];

        if (!((g > 3.1f) && (dC > 0.007f))) {
            if (lane == 0) { out[2 * n] = 0.0f; out[2 * n + 1] = 0.0f; }
            continue;                              // next point
        }

        // ---- gather 2000 samples into registers via int4 loads of bx/by.
        const int4* bx4p = (const int4*)(bxs + (size_t)n * DENSE);
        const int4* by4p = (const int4*)(bys + (size_t)n * DENSE);

        float sv[64];
        float mx = -1e30f, mn = 1e30f, stot = 0.0f;
        #pragma unroll
        for (int k = 0; k < 16; k++) {
            const int  c     = lane + (k << 5);
            const bool valid = (k < 15) || (c < CHUNKS);
            float v0 = -1e30f, v1 = -1e30f, v2 = -1e30f, v3 = -1e30f;  // pad
            if (valid) {
                const int4 b4 = bx4p[c];
                const int4 y4 = by4p[c];
                v0 = dch[base + y4.x * WW + b4.x];
                v1 = dch[base + y4.y * WW + b4.y];
                v2 = dch[base + y4.z * WW + b4.z];
                v3 = dch[base + y4.w * WW + b4.w];
                mx = fmaxf(fmaxf(mx, v0), fmaxf(v1, fmaxf(v2, v3)));
                mn = fminf(fminf(mn, v0), fminf(v1, fminf(v2, v3)));
                stot += (v0 + v1) + (v2 + v3);
            }
            sv[4 * k + 0] = v0;
            sv[4 * k + 1] = v1;
            sv[4 * k + 2] = v2;
            sv[4 * k + 3] = v3;
        }
        #pragma unroll
        for (int o = 16; o; o >>= 1) {
            mx   = fmaxf(mx, __shfl_xor_sync(0xFFFFFFFFu, mx, o));
            mn   = fminf(mn, __shfl_xor_sync(0xFFFFFFFFu, mn, o));
            stot +=          __shfl_xor_sync(0xFFFFFFFFu, stot, o);
        }

        // ---- 2-cluster 1-D k-means. kL > kS => |s-kL|<=|s-kS| <=> s >= (kL+kS)/2
        // (midpoint tie -> large cluster, matching dl<=ds). Bitwise fixed point =>
        // remaining reference iterations are identical -> exact early exit.
        float kL = mx, kS = mn;
        float lastCnt = 0.0f;
        #pragma unroll 1
        for (int it = 0; it < KMEAN; it++) {
            const float mid = 0.5f * (kL + kS);
            float s0 = 0.0f, s1 = 0.0f, c0 = 0.0f, c1 = 0.0f;
            #pragma unroll
            for (int k = 0; k < 64; k += 2) {
                const float a = sv[k], b = sv[k + 1];
                if (a >= mid) { s0 += a; c0 += 1.0f; }
                if (b >= mid) { s1 += b; c1 += 1.0f; }
            }
            float sumL = s0 + s1;
            float cntL = c0 + c1;
            #pragma unroll
            for (int o = 16; o; o >>= 1) {
                sumL += __shfl_xor_sync(0xFFFFFFFFu, sumL, o);
                cntL += __shfl_xor_sync(0xFFFFFFFFu, cntL, o);
            }
            const float nkL = __fdividef(sumL, cntL);
            const float nkS = __fdividef(stot - sumL, (float)DENSE - cntL);
            lastCnt = cntL;
            const bool conv = (nkL == kL) && (nkS == kS);
            kL = nkL; kS = nkS;
            if (conv) break;
        }

        const bool keep = ((kL - kS) > 0.005f) && (lastCnt > 5.0f);
        if (lane == 0) {
            const float kf = keep ? 1.0f : 0.0f;
            out[2 * n]     = kL * kf;
            out[2 * n + 1] = kS * kf;
        }
    }
}

extern "C" void kernel_launch(void* const* d_in, const int* in_sizes, int n_in,
                              void* d_out, int out_size)
{
    const float* disp = (const float*)d_in[0];
    const float* fore = (const float*)d_in[1];
    const int*   cxs  = (const int*)  d_in[2];
    const int*   cys  = (const int*)  d_in[3];
    const int*   bxs  = (const int*)  d_in[4];
    const int*   bys  = (const int*)  d_in[5];
    float*       out  = (float*)d_out;

    reset_kernel<<<1, 1>>>();
    // 4 blocks/SM residency at 128 regs/thread, 148 SMs -> 592 blocks, one wave.
    rsbsp_kernel<<<592, 128>>>(disp, fore, cxs, cys, bxs, bys, out);
}

// round 4
// speedup vs baseline: 1.0151x; 1.0151x over previous
#include <cuda_runtime.h>
#include <cuda_bf16.h>

#define BCH   10
#define HH    320
#define WW    1024
#define PTS   500
#define DENSE 2000
#define KMEAN 10
#define NPTS  (BCH * PTS)
#define CHUNKS (DENSE / 4)      // 500 int4 chunks per point

__device__ int g_count;
__device__ int g_queue[NPTS];

__global__ void reset_kernel() { g_count = 0; }

// ---- Phase 1: one THREAD per point. Validity check + output zeroing +
// compaction of valid indices into g_queue.
__global__ __launch_bounds__(128)
void valid_kernel(const float* __restrict__ disp,
                  const float* __restrict__ fore,
                  const int*   __restrict__ cxs,
                  const int*   __restrict__ cys,
                  float*       __restrict__ out)
{
    const int n = blockIdx.x * blockDim.x + threadIdx.x;
    if (n >= NPTS) return;

    out[2 * n]     = 0.0f;    // default; phase 2 overwrites valid rows
    out[2 * n + 1] = 0.0f;

    const int chan = n / PTS;
    const int cx   = cxs[n];
    const int cy   = cys[n];
    const float* dch = disp + (size_t)chan * (HH * WW);
    const float* fch = fore + (size_t)chan * (HH * WW);

    // maxpool3x3(|sobel_x(forepred)|) at (cy,cx): needs 5x5 forepred window.
    // Centers are >= 11 px from all borders -> no zeroArea / padding cases.
    float w[5][5];
    #pragma unroll
    for (int r = 0; r < 5; r++) {
        const float* p = fch + (size_t)(cy + r - 2) * WW + (cx - 2);
        #pragma unroll
        for (int c = 0; c < 5; c++) w[r][c] = p[c];
    }
    float best = 0.0f;
    #pragma unroll
    for (int r = 0; r < 3; r++) {
        #pragma unroll
        for (int c = 0; c < 3; c++) {
            const float a = w[r][c + 2] + 2.0f * w[r + 1][c + 2] + w[r + 2][c + 2];
            const float b = w[r][c]     + 2.0f * w[r + 1][c]     + w[r + 2][c];
            best = fmaxf(best, fabsf(a - b));
        }
    }
    const float dC = dch[(cy << 10) + cx];
    if ((best > 3.1f) && (dC > 0.007f)) {
        const int pos = atomicAdd(&g_count, 1);
        g_queue[pos] = n;
    }
}

// ---- Phase 2: one WARP per valid (compacted) point. Heavy warps are the
// first g_count warps -> all start in wave 1 -> full latency overlap.
__global__ __launch_bounds__(128, 4)
void kmeans_kernel(const float* __restrict__ disp,
                   const int*   __restrict__ cxs,
                   const int*   __restrict__ cys,
                   const int*   __restrict__ bxs,
                   const int*   __restrict__ bys,
                   float*       __restrict__ out)
{
    const int gwarp = (blockIdx.x * blockDim.x + threadIdx.x) >> 5;
    const int lane  = threadIdx.x & 31;
    if (gwarp >= g_count) return;

    const int n    = g_queue[gwarp];
    const int chan = n / PTS;
    const int cx   = cxs[n];
    const int cy   = cys[n];
    const float* dch = disp + (size_t)chan * (HH * WW);
    const int    base = (cy << 10) + cx;      // WW == 1024

    // gather 2000 samples into registers via int4 loads of bx/by
    const int4* bx4p = (const int4*)(bxs + (size_t)n * DENSE);
    const int4* by4p = (const int4*)(bys + (size_t)n * DENSE);

    float sv[64];
    float mx = -1e30f, mn = 1e30f, stot = 0.0f;
    #pragma unroll
    for (int k = 0; k < 16; k++) {
        const int  c     = lane + (k << 5);
        const bool valid = (k < 15) || (c < CHUNKS);   // compile-time true k<15
        float v0 = -1e30f, v1 = -1e30f, v2 = -1e30f, v3 = -1e30f;  // pad
        if (valid) {
            const int4 b4 = bx4p[c];
            const int4 y4 = by4p[c];
            v0 = dch[base + y4.x * WW + b4.x];
            v1 = dch[base + y4.y * WW + b4.y];
            v2 = dch[base + y4.z * WW + b4.z];
            v3 = dch[base + y4.w * WW + b4.w];
            mx = fmaxf(fmaxf(mx, v0), fmaxf(v1, fmaxf(v2, v3)));
            mn = fminf(fminf(mn, v0), fminf(v1, fminf(v2, v3)));
            stot += (v0 + v1) + (v2 + v3);
        }
        sv[4 * k + 0] = v0;
        sv[4 * k + 1] = v1;
        sv[4 * k + 2] = v2;
        sv[4 * k + 3] = v3;
    }
    #pragma unroll
    for (int o = 16; o; o >>= 1) {
        mx   = fmaxf(mx, __shfl_xor_sync(0xFFFFFFFFu, mx, o));
        mn   = fminf(mn, __shfl_xor_sync(0xFFFFFFFFu, mn, o));
        stot +=          __shfl_xor_sync(0xFFFFFFFFu, stot, o);
    }

    // 2-cluster 1-D k-means. kL > kS => |s-kL|<=|s-kS| <=> s >= (kL+kS)/2
    // (midpoint tie -> large cluster, matches dl<=ds). Bitwise fixed point =>
    // remaining reference iterations are no-ops -> exact early exit.
    float kL = mx, kS = mn;
    float lastCnt = 0.0f;
    #pragma unroll 1
    for (int it = 0; it < KMEAN; it++) {
        const float mid = 0.5f * (kL + kS);
        float s0 = 0.0f, s1 = 0.0f, c0 = 0.0f, c1 = 0.0f;
        #pragma unroll
        for (int k = 0; k < 64; k += 2) {
            const float a = sv[k], b = sv[k + 1];
            if (a >= mid) { s0 += a; c0 += 1.0f; }
            if (b >= mid) { s1 += b; c1 += 1.0f; }
        }
        float sumL = s0 + s1;
        float cntL = c0 + c1;
        #pragma unroll
        for (int o = 16; o; o >>= 1) {
            sumL += __shfl_xor_sync(0xFFFFFFFFu, sumL, o);
            cntL += __shfl_xor_sync(0xFFFFFFFFu, cntL, o);
        }
        const float nkL = __fdividef(sumL, cntL);
        const float nkS = __fdividef(stot - sumL, (float)DENSE - cntL);
        lastCnt = cntL;
        const bool conv = (nkL == kL) && (nkS == kS);
        kL = nkL; kS = nkS;
        if (conv) break;
    }

    const bool keep = ((kL - kS) > 0.005f) && (lastCnt > 5.0f);
    if (lane == 0) {
        const float kf = keep ? 1.0f : 0.0f;
        out[2 * n]     = kL * kf;
        out[2 * n + 1] = kS * kf;
    }
}

extern "C" void kernel_launch(void* const* d_in, const int* in_sizes, int n_in,
                              void* d_out, int out_size)
{
    const float* disp = (const float*)d_in[0];
    const float* fore = (const float*)d_in[1];
    const int*   cxs  = (const int*)  d_in[2];
    const int*   cys  = (const int*)  d_in[3];
    const int*   bxs  = (const int*)  d_in[4];
    const int*   bys  = (const int*)  d_in[5];
    float*       out  = (float*)d_out;

    reset_kernel<<<1, 1>>>();
    valid_kernel<<<(NPTS + 127) / 128, 128>>>(disp, fore, cxs, cys, out);
    // worst case: every point valid -> NPTS warps. Excess warps exit instantly.
    kmeans_kernel<<<(NPTS * 32 + 127) / 128, 128>>>(disp, cxs, cys, bxs, bys, out);
}